// round 1
// baseline (speedup 1.0000x reference)
#include <cuda_runtime.h>
#include <math.h>

#define N_NODES 20000
#define NHID 128
#define HEADS 4
#define HC (HEADS * NHID)          // 512
#define E_EDGES 320000
#define ETOT (E_EDGES + N_NODES)   // 340000
#define NLAYERS 4
#define NCLASS 40
#define NEG_SLOPE 0.2f
#define DT 1.0f
#define ALPHA 1.0f
#define GAMMA 1.0f

// d_out layout: [out (N*NCLASS)] [X_all (N*(L+1)*C)] [Y_all (N*(L+1)*C)]
#define OUT_OFF   0
#define XALL_OFF  (N_NODES * NCLASS)
#define YALL_OFF  (XALL_OFF + N_NODES * (NLAYERS + 1) * NHID)
#define LSTRIDE   ((NLAYERS + 1) * NHID)   // 640 per node in X_all/Y_all

// ------------------------- device scratch (no allocs allowed) ----------------
__device__ float g_h[N_NODES * HC];          // 41 MB
__device__ float g_X[N_NODES * NHID];
__device__ float g_Y[N_NODES * NHID];
__device__ float g_as[N_NODES * HEADS];
__device__ float g_ad[N_NODES * HEADS];
__device__ float g_ex[ETOT * HEADS];         // per-CSR-position edge values
__device__ float g_den[N_NODES * HEADS];
__device__ int   g_deg[N_NODES];
__device__ int   g_cursor[N_NODES];
__device__ int   g_off[N_NODES + 1];
__device__ int   g_csr_src[ETOT];

// ------------------------- setup kernels -------------------------------------
__global__ void k_zero_int2(int* a, int* b, int n) {
    int i = blockIdx.x * blockDim.x + threadIdx.x;
    if (i < n) { a[i] = 0; b[i] = 0; }
}

__global__ void k_count_deg(const int* __restrict__ dst) {
    int e = blockIdx.x * blockDim.x + threadIdx.x;
    if (e >= ETOT) return;
    int d = (e < E_EDGES) ? dst[e] : (e - E_EDGES);
    atomicAdd(&g_deg[d], 1);
}

// single-block exclusive scan over g_deg -> g_off (N=20000)
__global__ void k_scan() {
    __shared__ int s[1024];
    const int CH = (N_NODES + 1023) / 1024;  // 20
    int tid = threadIdx.x;
    int base = tid * CH;
    int sum = 0;
    for (int i = 0; i < CH; i++) {
        int idx = base + i;
        if (idx < N_NODES) sum += g_deg[idx];
    }
    s[tid] = sum;
    __syncthreads();
    for (int d = 1; d < 1024; d <<= 1) {
        int v = (tid >= d) ? s[tid - d] : 0;
        __syncthreads();
        s[tid] += v;
        __syncthreads();
    }
    int run = (tid == 0) ? 0 : s[tid - 1];
    for (int i = 0; i < CH; i++) {
        int idx = base + i;
        if (idx < N_NODES) { g_off[idx] = run; run += g_deg[idx]; }
    }
    if (tid == 1023) g_off[N_NODES] = run;
}

__global__ void k_scatter(const int* __restrict__ src, const int* __restrict__ dst) {
    int e = blockIdx.x * blockDim.x + threadIdx.x;
    if (e >= ETOT) return;
    int d, s;
    if (e < E_EDGES) { d = dst[e]; s = src[e]; }
    else { d = e - E_EDGES; s = d; }
    int pos = g_off[d] + atomicAdd(&g_cursor[d], 1);
    g_csr_src[pos] = s;
}

// init state + write layer-0 slices of X_all / Y_all
__global__ void k_init(const float* __restrict__ x, float* __restrict__ out) {
    int n = blockIdx.x;
    int t = threadIdx.x;
    float v = x[n * NHID + t];
    g_X[n * NHID + t] = v;
    g_Y[n * NHID + t] = v;
    out[XALL_OFF + n * LSTRIDE + t] = v;
    out[YALL_OFF + n * LSTRIDE + t] = v;
}

// ------------------------- GEMM: h = X (Nx128) @ W (128x512) ------------------
#define BM 128
#define BN 128
#define BK 8
#define TM 8
#define TN 8
__global__ __launch_bounds__(256) void k_gemm_h(const float* __restrict__ W) {
    __shared__ float As[BK][BM + 4];
    __shared__ float Bs[BK][BN + 4];
    const int K = NHID;
    int bn = blockIdx.x, bm = blockIdx.y;
    int tid = threadIdx.x;
    int tr = tid / 16, tc = tid % 16;
    int rowBase = bm * BM;
    float acc[TM][TN];
#pragma unroll
    for (int i = 0; i < TM; i++)
#pragma unroll
        for (int j = 0; j < TN; j++) acc[i][j] = 0.f;

    for (int k0 = 0; k0 < K; k0 += BK) {
#pragma unroll
        for (int i = 0; i < 4; i++) {
            int idx = tid + i * 256;                     // 0..1023
            int r = idx / BK, kk = idx % BK;             // A tile
            int arow = rowBase + r;
            As[kk][r] = (arow < N_NODES) ? g_X[arow * K + k0 + kk] : 0.f;
            int brow = idx / BN, bcol = idx % BN;        // B tile
            Bs[brow][bcol] = W[(k0 + brow) * HC + bn * BN + bcol];
        }
        __syncthreads();
#pragma unroll
        for (int kk = 0; kk < BK; kk++) {
            float a[TM], b[TN];
#pragma unroll
            for (int i = 0; i < TM; i++) a[i] = As[kk][tr * TM + i];
#pragma unroll
            for (int j = 0; j < TN; j++) b[j] = Bs[kk][tc * TN + j];
#pragma unroll
            for (int i = 0; i < TM; i++)
#pragma unroll
                for (int j = 0; j < TN; j++) acc[i][j] += a[i] * b[j];
        }
        __syncthreads();
    }
#pragma unroll
    for (int i = 0; i < TM; i++) {
        int r = rowBase + tr * TM + i;
        if (r < N_NODES) {
#pragma unroll
            for (int j = 0; j < TN; j++)
                g_h[r * HC + bn * BN + tc * TN + j] = acc[i][j];
        }
    }
}

// ------------------------- attention coefficients -----------------------------
__global__ void k_attn(const float* __restrict__ att_src, const float* __restrict__ att_dst) {
    int n = blockIdx.x;
    int tid = threadIdx.x;               // 128
    int hd = tid >> 5, lane = tid & 31;
    const float* hr = g_h + n * HC + hd * NHID;
    float s1 = 0.f, s2 = 0.f;
#pragma unroll
    for (int i = lane; i < NHID; i += 32) {
        float v = hr[i];
        s1 += v * att_src[hd * NHID + i];
        s2 += v * att_dst[hd * NHID + i];
    }
#pragma unroll
    for (int o = 16; o; o >>= 1) {
        s1 += __shfl_xor_sync(0xffffffffu, s1, o);
        s2 += __shfl_xor_sync(0xffffffffu, s2, o);
    }
    if (lane == 0) {
        g_as[n * HEADS + hd] = s1;
        g_ad[n * HEADS + hd] = s2;
    }
}

// ------------------------- scatter softmax (warp per node) --------------------
__global__ void k_softmax() {
    int warps_per_blk = blockDim.x >> 5;
    int n = blockIdx.x * warps_per_blk + (threadIdx.x >> 5);
    if (n >= N_NODES) return;
    int lane = threadIdx.x & 31;
    int st = g_off[n], en = g_off[n + 1];
    float4 ad4 = ((const float4*)g_ad)[n];
    float mx0 = -1e30f, mx1 = -1e30f, mx2 = -1e30f, mx3 = -1e30f;
    for (int p = st + lane; p < en; p += 32) {
        int s = g_csr_src[p];
        float4 as4 = ((const float4*)g_as)[s];
        float e0 = as4.x + ad4.x, e1 = as4.y + ad4.y, e2 = as4.z + ad4.z, e3 = as4.w + ad4.w;
        e0 = e0 > 0.f ? e0 : e0 * NEG_SLOPE;
        e1 = e1 > 0.f ? e1 : e1 * NEG_SLOPE;
        e2 = e2 > 0.f ? e2 : e2 * NEG_SLOPE;
        e3 = e3 > 0.f ? e3 : e3 * NEG_SLOPE;
        float4 ev = make_float4(e0, e1, e2, e3);
        ((float4*)g_ex)[p] = ev;
        mx0 = fmaxf(mx0, e0); mx1 = fmaxf(mx1, e1);
        mx2 = fmaxf(mx2, e2); mx3 = fmaxf(mx3, e3);
    }
#pragma unroll
    for (int o = 16; o; o >>= 1) {
        mx0 = fmaxf(mx0, __shfl_xor_sync(0xffffffffu, mx0, o));
        mx1 = fmaxf(mx1, __shfl_xor_sync(0xffffffffu, mx1, o));
        mx2 = fmaxf(mx2, __shfl_xor_sync(0xffffffffu, mx2, o));
        mx3 = fmaxf(mx3, __shfl_xor_sync(0xffffffffu, mx3, o));
    }
    float s0 = 0.f, s1 = 0.f, s2 = 0.f, s3 = 0.f;
    for (int p = st + lane; p < en; p += 32) {
        float4 ev = ((const float4*)g_ex)[p];
        float x0 = __expf(ev.x - mx0), x1 = __expf(ev.y - mx1);
        float x2 = __expf(ev.z - mx2), x3 = __expf(ev.w - mx3);
        ((float4*)g_ex)[p] = make_float4(x0, x1, x2, x3);
        s0 += x0; s1 += x1; s2 += x2; s3 += x3;
    }
#pragma unroll
    for (int o = 16; o; o >>= 1) {
        s0 += __shfl_xor_sync(0xffffffffu, s0, o);
        s1 += __shfl_xor_sync(0xffffffffu, s1, o);
        s2 += __shfl_xor_sync(0xffffffffu, s2, o);
        s3 += __shfl_xor_sync(0xffffffffu, s3, o);
    }
    if (lane == 0) ((float4*)g_den)[n] = make_float4(s0, s1, s2, s3);
}

// ------------------------- aggregate + GraphCON update ------------------------
__global__ __launch_bounds__(128) void k_aggregate(const float* __restrict__ bias,
                                                   float* __restrict__ out, int layer) {
    int n = blockIdx.x;
    int t = threadIdx.x;                 // 128, channel t of every head
    int st = g_off[n], en = g_off[n + 1];
    float acc0 = 0.f, acc1 = 0.f, acc2 = 0.f, acc3 = 0.f;
    for (int p = st; p < en; p++) {
        int s = g_csr_src[p];
        float4 ev = ((const float4*)g_ex)[p];
        const float* hs = g_h + s * HC;
        acc0 += ev.x * hs[t];
        acc1 += ev.y * hs[NHID + t];
        acc2 += ev.z * hs[2 * NHID + t];
        acc3 += ev.w * hs[3 * NHID + t];
    }
    float4 dn = ((const float4*)g_den)[n];
    float g0 = acc0 / dn.x + bias[t];
    float g1 = acc1 / dn.y + bias[NHID + t];
    float g2 = acc2 / dn.z + bias[2 * NHID + t];
    float g3 = acc3 / dn.w + bias[3 * NHID + t];
    // elu
    g0 = g0 > 0.f ? g0 : (expf(g0) - 1.f);
    g1 = g1 > 0.f ? g1 : (expf(g1) - 1.f);
    g2 = g2 > 0.f ? g2 : (expf(g2) - 1.f);
    g3 = g3 > 0.f ? g3 : (expf(g3) - 1.f);
    __shared__ float sg[HC];
    sg[t] = g0; sg[NHID + t] = g1; sg[2 * NHID + t] = g2; sg[3 * NHID + t] = g3;
    __syncthreads();
    // agg[c] = mean of flat[4c..4c+3]  (view(N,-1,H).mean(-1) on head-major flat)
    float4 q = ((const float4*)sg)[t];
    float agg = 0.25f * (q.x + q.y + q.z + q.w);
    float x = g_X[n * NHID + t];
    float y = g_Y[n * NHID + t];
    float y2 = y + DT * (agg - ALPHA * y - GAMMA * x);
    float x2 = x + DT * y2;
    g_X[n * NHID + t] = x2;
    g_Y[n * NHID + t] = y2;
    out[XALL_OFF + n * LSTRIDE + (layer + 1) * NHID + t] = x2;
    out[YALL_OFF + n * LSTRIDE + (layer + 1) * NHID + t] = y2;
}

// ------------------------- output projection ----------------------------------
__global__ void k_outproj(const float* __restrict__ Wr, const float* __restrict__ br,
                          float* __restrict__ out) {
    __shared__ float xs[NHID];
    int n = blockIdx.x;
    int t = threadIdx.x;                 // 128
    xs[t] = g_X[n * NHID + t];
    __syncthreads();
    if (t < NCLASS) {
        const float* w = Wr + t * NHID;
        float acc = 0.f;
#pragma unroll 8
        for (int k = 0; k < NHID; k++) acc += xs[k] * w[k];
        out[OUT_OFF + n * NCLASS + t] = acc + br[t];
    }
}

// ------------------------- launch ---------------------------------------------
extern "C" void kernel_launch(void* const* d_in, const int* in_sizes, int n_in,
                              void* d_out, int out_size) {
    const float* x       = (const float*)d_in[0];
    const int*   src     = (const int*)d_in[1];
    const int*   dst     = (const int*)d_in[2];
    const float* W       = (const float*)d_in[3];
    const float* att_src = (const float*)d_in[4];
    const float* att_dst = (const float*)d_in[5];
    const float* bias    = (const float*)d_in[6];
    const float* Wr      = (const float*)d_in[7];
    const float* br      = (const float*)d_in[8];
    float* out = (float*)d_out;

    int *deg_p, *cur_p;
    cudaGetSymbolAddress((void**)&deg_p, g_deg);
    cudaGetSymbolAddress((void**)&cur_p, g_cursor);

    // ---- build CSR by destination (once per call) ----
    k_zero_int2<<<(N_NODES + 255) / 256, 256>>>(deg_p, cur_p, N_NODES);
    k_count_deg<<<(ETOT + 255) / 256, 256>>>(dst);
    k_scan<<<1, 1024>>>();
    k_scatter<<<(ETOT + 255) / 256, 256>>>(src, dst);

    // ---- init state ----
    k_init<<<N_NODES, NHID>>>(x, out);

    dim3 ggrid(HC / BN, (N_NODES + BM - 1) / BM);
    for (int l = 0; l < NLAYERS; l++) {
        k_gemm_h<<<ggrid, 256>>>(W);
        k_attn<<<N_NODES, 128>>>(att_src, att_dst);
        k_softmax<<<(N_NODES * 32 + 255) / 256, 256>>>();
        k_aggregate<<<N_NODES, 128>>>(bias, out, l);
    }
    k_outproj<<<N_NODES, 128>>>(Wr, br, out);
}